// round 17
// baseline (speedup 1.0000x reference)
#include <cuda_runtime.h>
#include <cuda_bf16.h>
#include <math.h>

// Problem constants
#define K_ 128
#define J_ 4
#define N_ 64
#define R_ 32
#define T_ 32
#define S_ 256
#define A_ 4
#define D_ 64
#define Z_ (K_*J_)   // 512
#define TM1 (T_-1)   // 31
#define RP1 (R_+1)   // 33

// Output segment offsets (floats)
#define O0 0u
#define O1 4224u
#define O2 8448u
#define O3 12672u
#define O4 16896u
#define O5 287232u
#define O6 291200u
#define O7 295168u
#define O8 549120u
#define O9 4612352u
#define O10 4612480u
#define O11 4612608u

#define LOG10F 2.302585092994045684f
#define LOG4F  1.3862943611198906f

// block classes
#define NB_KA  (2*K_)          // 256
#define NB_KB  (NB_KA + Z_)    // 768
#define NB_ALL (NB_KB + K_)    // 896

// ---------------- scratch ----------------
__device__ float g_ckept[K_*T_];
__device__ float g_llnew[Z_];
__device__ float g_P1[Z_*16];
__device__ float g_P2[Z_*16];
__device__ int   g_cnt[K_];       // producer arrivals (selector resets)
__device__ int   g_flag[K_];      // selection published (last kA copier resets)
__device__ int   g_done[K_];      // kA copier arrivals
__device__ int4  g_selinfo[K_];   // {gk, i1, i2, zs}

__device__ __forceinline__ float f_logdf(const float* logdf, int l) {
    int di = 2*l - 3;
    di = max(0, min(2*N_ - 1, di));
    return logdf[di];
}

// ---------------- the one kernel ----------------
// [0,256): kA halves (compute ckept for 16 rows, then spin + copy those rows).
// [256,768): kB candidates (never wait).
// [768,896): selectors (spin cnt==6; select + scalars + node30 + merge history).
__global__ void __launch_bounds__(256, 6) kall(
        const int* __restrict__ indexes,
        const int* __restrict__ lc, const int* __restrict__ hashes,
        const float* __restrict__ embt, const float* __restrict__ lf,
        const float* __restrict__ Wstat,
        const int* __restrict__ idx1a, const int* __restrict__ idx2a,
        const float* __restrict__ br1, const float* __restrict__ br2,
        const float* __restrict__ embJ, const float* __restrict__ Wq,
        const float* __restrict__ b1r, const float* __restrict__ b2r,
        const float* __restrict__ log_pi, const float* __restrict__ logvp,
        const float* __restrict__ gumbel, const float* __restrict__ logdf,
        const int* __restrict__ m1r, const int* __restrict__ m2r,
        const float* __restrict__ embr,
        float* __restrict__ out) {
    int tid = threadIdx.x;
    int warp = tid >> 5, lane = tid & 31;

    if (blockIdx.x < NB_KA) {
        // ===== kA half: rows h*16 .. h*16+15 of particle k =====
        int k = blockIdx.x >> 1, h = blockIdx.x & 1;
        int gk = indexes[k];
        int tA = h*16 + warp;
        int tB = tA + 8;

        const float2* eA2 = (const float2*)(embt + (size_t)(gk*T_ + tA)*D_);
        const float2* eB2 = (const float2*)(embt + (size_t)(gk*T_ + tB)*D_);
        float2 ea = eA2[lane];
        float2 eb = eB2[lane];
        const float4* w4 = (const float4*)Wstat;
        float4 wa = w4[2*lane], wb = w4[2*lane + 1];
        float a0 = ea.x*wa.x + ea.y*wb.x;
        float a1 = ea.x*wa.y + ea.y*wb.y;
        float a2 = ea.x*wa.z + ea.y*wb.z;
        float a3 = ea.x*wa.w + ea.y*wb.w;
        float b0 = eb.x*wa.x + eb.y*wb.x;
        float b1 = eb.x*wa.y + eb.y*wb.y;
        float b2 = eb.x*wa.z + eb.y*wb.z;
        float b3 = eb.x*wa.w + eb.y*wb.w;
        #pragma unroll
        for (int off = 16; off; off >>= 1) {
            a0 += __shfl_xor_sync(0xffffffffu, a0, off);
            a1 += __shfl_xor_sync(0xffffffffu, a1, off);
            a2 += __shfl_xor_sync(0xffffffffu, a2, off);
            a3 += __shfl_xor_sync(0xffffffffu, a3, off);
            b0 += __shfl_xor_sync(0xffffffffu, b0, off);
            b1 += __shfl_xor_sync(0xffffffffu, b1, off);
            b2 += __shfl_xor_sync(0xffffffffu, b2, off);
            b3 += __shfl_xor_sync(0xffffffffu, b3, off);
        }
        float mA = fmaxf(fmaxf(a0, a1), fmaxf(a2, a3));
        float pA0 = __expf(a0 - mA), pA1 = __expf(a1 - mA);
        float pA2 = __expf(a2 - mA), pA3 = __expf(a3 - mA);
        float invA = 1.f / (pA0 + pA1 + pA2 + pA3);
        pA0 *= invA; pA1 *= invA; pA2 *= invA; pA3 *= invA;
        float mB = fmaxf(fmaxf(b0, b1), fmaxf(b2, b3));
        float pB0 = __expf(b0 - mB), pB1 = __expf(b1 - mB);
        float pB2 = __expf(b2 - mB), pB3 = __expf(b3 - mB);
        float invB = 1.f / (pB0 + pB1 + pB2 + pB3);
        pB0 *= invB; pB1 *= invB; pB2 *= invB; pB3 *= invB;

        const float4* rowA = (const float4*)(lf + (size_t)(gk*T_ + tA)*S_*A_);
        const float4* rowB = (const float4*)(lf + (size_t)(gk*T_ + tB)*S_*A_);
        float prodA0 = 1.f, prodA1v = 1.f, prodB0 = 1.f, prodB1v = 1.f;
        #pragma unroll
        for (int g = 0; g < 4; g++) {
            float4 vA0 = rowA[lane + 32*(2*g)];
            float4 vA1 = rowA[lane + 32*(2*g + 1)];
            float4 vB0 = rowB[lane + 32*(2*g)];
            float4 vB1 = rowB[lane + 32*(2*g + 1)];
            float dA0 = pA0*__expf(vA0.x) + pA1*__expf(vA0.y)
                      + pA2*__expf(vA0.z) + pA3*__expf(vA0.w);
            float dA1 = pA0*__expf(vA1.x) + pA1*__expf(vA1.y)
                      + pA2*__expf(vA1.z) + pA3*__expf(vA1.w);
            float dB0 = pB0*__expf(vB0.x) + pB1*__expf(vB0.y)
                      + pB2*__expf(vB0.z) + pB3*__expf(vB0.w);
            float dB1 = pB0*__expf(vB1.x) + pB1*__expf(vB1.y)
                      + pB2*__expf(vB1.z) + pB3*__expf(vB1.w);
            prodA0 *= dA0; prodA1v *= dA1;
            prodB0 *= dB0; prodB1v *= dB1;
        }
        float accA = __logf(prodA0 * prodA1v);
        float accB = __logf(prodB0 * prodB1v);
        #pragma unroll
        for (int off = 16; off; off >>= 1) {
            accA += __shfl_xor_sync(0xffffffffu, accA, off);
            accB += __shfl_xor_sync(0xffffffffu, accB, off);
        }
        if (lane == 0) {
            g_ckept[k*T_ + tA] = accA;
            g_ckept[k*T_ + tB] = accB;
        }
        __syncthreads();
        if (tid == 0) { __threadfence(); atomicAdd(&g_cnt[k], 1); }

        // ---- spin for this particle's selection (producers never wait;
        //      the selection arrives once the particle's 4 kB blocks finish) ----
        if (tid == 0) {
            while (*((volatile int*)&g_flag[k]) == 0) __nanosleep(32);
            __threadfence();
        }
        __syncthreads();
        int4 si = g_selinfo[k];
        int i1 = si.y, i2 = si.z;
        int ra = min(i1, i2), rb = max(i1, i2);

        // ---- copy my 16 rows (L1-hot: just streamed them) to shifted slots ----
        #pragma unroll 4
        for (int r = 0; r < 16; r++) {
            int t = h*16 + r;
            if (t == ra || t == rb) continue;
            int n = t - (t > ra) - (t > rb);
            float4 v = ((const float4*)(lf + (size_t)(gk*T_ + t)*S_*A_))[tid];
            ((float4*)(out + O8 + (size_t)(k*TM1 + n)*S_*A_))[tid] = v;
        }
        // embt rows (16 x 64 = 1024 elems, 4/thread)
        #pragma unroll
        for (int e = tid; e < 16*D_; e += 256) {
            int r = e >> 6, d = e & 63;
            int t = h*16 + r;
            if (t == ra || t == rb) continue;
            int n = t - (t > ra) - (t > rb);
            out[O7 + (size_t)(k*TM1 + n)*D_ + d] = embt[(size_t)(gk*T_ + t)*D_ + d];
        }
        if (tid < 16) {
            int t = h*16 + tid;
            if (t != ra && t != rb) {
                int n = t - (t > ra) - (t > rb);
                out[O5 + k*TM1 + n] = (float)lc[gk*T_ + t];
                out[O6 + k*TM1 + n] = (float)hashes[gk*T_ + t];
            }
        }
        // last kA copier of particle k resets flag/done for next replay
        __syncthreads();
        if (tid == 0) {
            int old = atomicAdd(&g_done[k], 1);
            if (old == 1) { g_flag[k] = 0; g_done[k] = 0; }
        }
    } else if (blockIdx.x < NB_KB) {
        // ===== kB candidate z (never waits) =====
        int z = blockIdx.x - NB_KA;
        int k = z / J_;
        int gk = indexes[k];
        __shared__ float slog[20];
        __shared__ float sP1[16], sP2[16], sstat[4];
        __shared__ float s_red[8];

        int i1 = idx1a[z], i2 = idx2a[z];
        float bb1 = br1[z], bb2 = br2[z];

        const float4* r1 = (const float4*)(lf + (size_t)(gk*T_ + i1)*S_*A_);
        const float4* r2 = (const float4*)(lf + (size_t)(gk*T_ + i2)*S_*A_);
        float4 w1 = r1[tid], w2 = r2[tid];
        float e10=__expf(w1.x), e11=__expf(w1.y), e12=__expf(w1.z), e13=__expf(w1.w);
        float e20=__expf(w2.x), e21=__expf(w2.y), e22=__expf(w2.z), e23=__expf(w2.w);

        if (warp < 5) {
            const float2* emb2 = (const float2*)(embJ + (size_t)z*D_);
            float2 e = emb2[lane];
            float l0, l1, l2, l3;
            if (warp < 4) {
                int col = 4*warp;
                const float* Wq0 = Wq + (2*lane)*16 + col;
                const float* Wq1 = Wq + (2*lane + 1)*16 + col;
                l0 = e.x*Wq0[0] + e.y*Wq1[0];
                l1 = e.x*Wq0[1] + e.y*Wq1[1];
                l2 = e.x*Wq0[2] + e.y*Wq1[2];
                l3 = e.x*Wq0[3] + e.y*Wq1[3];
            } else {
                const float4* ws4 = (const float4*)Wstat;
                float4 wsa = ws4[2*lane], wsb = ws4[2*lane + 1];
                l0 = e.x*wsa.x + e.y*wsb.x;
                l1 = e.x*wsa.y + e.y*wsb.y;
                l2 = e.x*wsa.z + e.y*wsb.z;
                l3 = e.x*wsa.w + e.y*wsb.w;
            }
            #pragma unroll
            for (int off = 16; off; off >>= 1) {
                l0 += __shfl_xor_sync(0xffffffffu, l0, off);
                l1 += __shfl_xor_sync(0xffffffffu, l1, off);
                l2 += __shfl_xor_sync(0xffffffffu, l2, off);
                l3 += __shfl_xor_sync(0xffffffffu, l3, off);
            }
            if (lane == 0) {
                slog[4*warp + 0] = l0;
                slog[4*warp + 1] = l1;
                slog[4*warp + 2] = l2;
                slog[4*warp + 3] = l3;
            }
        }
        __syncthreads();

        if (warp == 0) {
            float logit = (lane < 20) ? slog[lane] : 0.f;
            {
                float mm = fmaxf(logit, __shfl_xor_sync(0xffffffffu, logit, 1));
                mm = fmaxf(mm, __shfl_xor_sync(0xffffffffu, mm, 2));
                float ex = __expf(logit - mm);
                float ttl = ex + __shfl_xor_sync(0xffffffffu, ex, 1);
                ttl += __shfl_xor_sync(0xffffffffu, ttl, 2);
                if (lane >= 16 && lane < 20) sstat[lane - 16] = ex / ttl;
            }
            int e = lane & 15, r = e >> 2, c = e & 3;
            float qoff = 0.f;
            if (lane < 16) {
                float x = logit;
                float sp = fmaxf(x, 0.f) + log1pf(__expf(-fabsf(x)));
                qoff = (r == c) ? 0.f : sp;
            }
            float s1 = qoff + __shfl_xor_sync(0xffffffffu, qoff, 1);
            float rs = s1 + __shfl_xor_sync(0xffffffffu, s1, 2);
            float Qown = (r == c) ? -rs : qoff;
            float Qe = __shfl_sync(0xffffffffu, Qown, lane & 15);

            int base = lane & 16;
            float bsc = ((lane < 16) ? bb1 : bb2) * 0.125f;
            float Av = Qe * bsc;
            float Ev = Av + ((r == c) ? 1.f : 0.f);
            float Tm = Av;
            #pragma unroll
            for (int n = 2; n <= 7; n++) {
                float s = 0.f;
                #pragma unroll
                for (int j = 0; j < 4; j++) {
                    float trj = __shfl_sync(0xffffffffu, Tm, base + (r<<2) + j);
                    float ajc = __shfl_sync(0xffffffffu, Av, base + (j<<2) + c);
                    s += trj * ajc;
                }
                Tm = s * (1.f / (float)n);
                Ev += Tm;
            }
            #pragma unroll
            for (int qq = 0; qq < 3; qq++) {
                float s = 0.f;
                #pragma unroll
                for (int j = 0; j < 4; j++) {
                    float erj = __shfl_sync(0xffffffffu, Ev, base + (r<<2) + j);
                    float ejc = __shfl_sync(0xffffffffu, Ev, base + (j<<2) + c);
                    s += erj * ejc;
                }
                Ev = s;
            }
            Ev = fmaxf(Ev, 1e-30f);
            if (lane < 16) { sP1[e] = Ev; g_P1[z*16 + e] = Ev; }
            else           { sP2[e] = Ev; g_P2[z*16 + e] = Ev; }
        }
        __syncthreads();
        {
            float tot = 0.f;
            #pragma unroll
            for (int a = 0; a < 4; a++) {
                float m1 = sP1[a*4+0]*e10 + sP1[a*4+1]*e11 + sP1[a*4+2]*e12 + sP1[a*4+3]*e13;
                float m2 = sP2[a*4+0]*e20 + sP2[a*4+1]*e21 + sP2[a*4+2]*e22 + sP2[a*4+3]*e23;
                tot += m1 * m2 * sstat[a];
            }
            float val = __logf(tot);
            #pragma unroll
            for (int off = 16; off; off >>= 1)
                val += __shfl_down_sync(0xffffffffu, val, off);
            if (lane == 0) s_red[warp] = val;
        }
        __syncthreads();
        if (tid == 0) {
            float s = 0.f;
            #pragma unroll
            for (int w = 0; w < 8; w++) s += s_red[w];
            g_llnew[z] = s;
            __threadfence();
            atomicAdd(&g_cnt[k], 1);
        }
    } else {
        // ===== selector + finisher block for particle k (256 threads) =====
        int k = blockIdx.x - NB_KB;
        int gk = indexes[k];
        __shared__ int s_i1, s_i2, s_zs;
        __shared__ float sP1[16], sP2[16];

        if (tid == 0) {
            while (*((volatile int*)&g_cnt[k]) < 6) __nanosleep(32);
            __threadfence();
        }
        __syncthreads();

        if (warp == 0) {
            float ck = g_ckept[k*T_ + lane];
            int l = lc[gk*T_ + lane];
            float fl = f_logdf(logdf, l);
            float cc = (l > 1) ? 1.f : 0.f;
            float sb = b1r[gk*R_ + lane] + b2r[gk*R_ + lane];
            #pragma unroll
            for (int off = 16; off; off >>= 1) {
                ck += __shfl_down_sync(0xffffffffu, ck, off);
                fl += __shfl_down_sync(0xffffffffu, fl, off);
                cc += __shfl_down_sync(0xffffffffu, cc, off);
                sb += __shfl_down_sync(0xffffffffu, sb, off);
            }
            float s_ct   = __shfl_sync(0xffffffffu, ck, 0);
            float s_flcT = __shfl_sync(0xffffffffu, fl, 0);
            float s_cT   = __shfl_sync(0xffffffffu, cc, 0);
            float s_sb   = __shfl_sync(0xffffffffu, sb, 0);

            float lw = -1e30f, lpn = 0.f, loglik = 0.f, gum = -1e30f;
            if (lane < J_) {
                int zc = k*J_ + lane;
                int c1 = idx1a[zc], c2 = idx2a[zc];
                loglik = s_ct - g_ckept[k*T_ + c1] - g_ckept[k*T_ + c2] + g_llnew[zc];
                float lbp = 2.f * (float)RP1 * LOG10F - 10.f * (s_sb + br1[zc] + br2[zc]);
                int l1 = lc[gk*T_ + c1], l2 = lc[gk*T_ + c2];
                float flcnew = s_flcT - f_logdf(logdf, l1) - f_logdf(logdf, l2)
                             + f_logdf(logdf, l1 + l2);
                float cnt = s_cT - (float)(l1 > 1) - (float)(l2 > 1) + 1.f;
                lpn = loglik + lbp - flcnew;
                lw = lpn - log_pi[gk] + __logf(cnt) - logvp[zc];
                gum = lw + gumbel[zc];
            }
            float m = lw;
            m = fmaxf(m, __shfl_xor_sync(0xffffffffu, m, 1));
            m = fmaxf(m, __shfl_xor_sync(0xffffffffu, m, 2));
            float ex = (lane < J_) ? __expf(lw - m) : 0.f;
            float se = ex + __shfl_xor_sync(0xffffffffu, ex, 1);
            se += __shfl_xor_sync(0xffffffffu, se, 2);

            float g0 = __shfl_sync(0xffffffffu, gum, 0);
            float g1 = __shfl_sync(0xffffffffu, gum, 1);
            float g2 = __shfl_sync(0xffffffffu, gum, 2);
            float g3 = __shfl_sync(0xffffffffu, gum, 3);
            int best = 0; float bv = g0;
            if (g1 > bv) { bv = g1; best = 1; }
            if (g2 > bv) { bv = g2; best = 2; }
            if (g3 > bv) { bv = g3; best = 3; }
            float lpn_b  = __shfl_sync(0xffffffffu, lpn, best);
            float llik_b = __shfl_sync(0xffffffffu, loglik, best);

            if (lane == 0) {
                int zs = k*J_ + best;
                g_selinfo[k] = make_int4(gk, idx1a[zs], idx2a[zs], zs);
                s_zs = zs; s_i1 = idx1a[zs]; s_i2 = idx2a[zs];
                out[O10 + k] = m + __logf(se) - LOG4F;
                out[O9 + k]  = lpn_b;
                out[O11 + k] = llik_b;
                g_cnt[k] = 0;                    // reset for next replay
                __threadfence();                 // publish selinfo
                *((volatile int*)&g_flag[k]) = 1;
            }
        }
        __syncthreads();
        int i1 = s_i1, i2 = s_i2, zs = s_zs;

        // ---- node 30: lf compute + embt + lc/h ----
        if (tid < 16) sP1[tid] = g_P1[zs*16 + tid];
        else if (tid < 32) sP2[tid-16] = g_P2[zs*16 + tid - 16];
        float4 w1 = ((const float4*)(lf + (size_t)(gk*T_ + i1)*S_*A_))[tid];
        float4 w2 = ((const float4*)(lf + (size_t)(gk*T_ + i2)*S_*A_))[tid];
        __syncthreads();
        {
            float e10=__expf(w1.x), e11=__expf(w1.y), e12=__expf(w1.z), e13=__expf(w1.w);
            float e20=__expf(w2.x), e21=__expf(w2.y), e22=__expf(w2.z), e23=__expf(w2.w);
            float4 res;
            float* rp = (float*)&res;
            #pragma unroll
            for (int aa = 0; aa < 4; aa++) {
                float m1 = sP1[aa*4+0]*e10 + sP1[aa*4+1]*e11 + sP1[aa*4+2]*e12 + sP1[aa*4+3]*e13;
                float m2 = sP2[aa*4+0]*e20 + sP2[aa*4+1]*e21 + sP2[aa*4+2]*e22 + sP2[aa*4+3]*e23;
                rp[aa] = __logf(m1) + __logf(m2);
            }
            ((float4*)(out + O8 + (size_t)(k*TM1 + 30)*S_*A_))[tid] = res;
        }
        if (tid < D_) out[O7 + (size_t)(k*TM1 + 30)*D_ + tid] = embJ[(size_t)zs*D_ + tid];
        if (tid == 0) {
            int l1 = lc[gk*T_ + i1], l2 = lc[gk*T_ + i2];
            out[O5 + k*TM1 + 30] = (float)(l1 + l2);
            int h1 = hashes[gk*T_ + i1], h2 = hashes[gk*T_ + i2];
            int mn = min(h1, h2), mx = max(h1, h2);
            unsigned int hh = ((unsigned int)mn * 1000003u + (unsigned int)mx) * 40503u + 2531011u;
            out[O6 + k*TM1 + 30] = (float)(int)hh;
        }
        // ---- merge-history scalars ----
        if (tid >= 64 && tid < 64 + RP1) {
            int r = tid - 64;
            float mv1, mv2, vb1, vb2;
            if (r < R_) {
                mv1 = (float)m1r[gk*R_ + r];
                mv2 = (float)m2r[gk*R_ + r];
                vb1 = b1r[gk*R_ + r];
                vb2 = b2r[gk*R_ + r];
            } else {
                mv1 = (float)i1; mv2 = (float)i2;
                vb1 = br1[zs];   vb2 = br2[zs];
            }
            out[O0 + k*RP1 + r] = mv1;
            out[O1 + k*RP1 + r] = mv2;
            out[O2 + k*RP1 + r] = vb1;
            out[O3 + k*RP1 + r] = vb2;
        }
        // ---- embr copy: 528 float4 ----
        {
            const float4* s4 = (const float4*)(embr + (size_t)gk*R_*D_);
            float4* d4 = (float4*)(out + O4 + (size_t)k*RP1*D_);
            d4[tid] = s4[tid];
            d4[tid + 256] = s4[tid + 256];
            if (tid < 16) {
                const float4* j4 = (const float4*)(embJ + (size_t)zs*D_);
                d4[512 + tid] = j4[tid];
            }
        }
    }
}

// ---------------- launch ----------------
extern "C" void kernel_launch(void* const* d_in, const int* in_sizes, int n_in,
                              void* d_out, int out_size) {
    const int*   indexes = (const int*)  d_in[0];
    const int*   m1r     = (const int*)  d_in[1];
    const int*   m2r     = (const int*)  d_in[2];
    const float* b1r     = (const float*)d_in[3];
    const float* b2r     = (const float*)d_in[4];
    const float* embr    = (const float*)d_in[5];
    const int*   lc      = (const int*)  d_in[6];
    const int*   hashes  = (const int*)  d_in[7];
    const float* embt    = (const float*)d_in[8];
    const float* lf      = (const float*)d_in[9];
    const float* log_pi  = (const float*)d_in[10];
    const int*   idx1a   = (const int*)  d_in[11];
    const int*   idx2a   = (const int*)  d_in[12];
    const float* br1     = (const float*)d_in[13];
    const float* br2     = (const float*)d_in[14];
    const float* embJ    = (const float*)d_in[15];
    const float* logvp   = (const float*)d_in[16];
    const float* gumbel  = (const float*)d_in[17];
    const float* Wq      = (const float*)d_in[18];
    const float* Wstat   = (const float*)d_in[19];
    const float* logdf   = (const float*)d_in[20];
    float* out = (float*)d_out;

    kall<<<NB_ALL, 256>>>(indexes, lc, hashes, embt, lf, Wstat,
                          idx1a, idx2a, br1, br2, embJ, Wq,
                          b1r, b2r, log_pi, logvp, gumbel, logdf,
                          m1r, m2r, embr, out);
}